// round 6
// baseline (speedup 1.0000x reference)
#include <cuda_runtime.h>

// Problem constants
#define NB   16      // batch
#define CI   128     // in channels
#define CO   256     // out channels
#define TT   128     // time
#define VV   25      // joints
#define WW   11      // parts
#define KG   3       // graph kernels
#define GG   8       // groups
#define MM   2048    // NB*TT
#define KK   3200    // VV*CI
#define NN   2816    // CO*WW
#define BN_EPS 1e-5f

// Scratch (static device globals — allocation-free contract)
__device__ float g_Xs[(size_t)MM * KK];     // 26 MB : x transposed to [(n,t), (v,i)]
__device__ float g_Wtot[(size_t)KK * NN];   // 36 MB : fused weight [(v,i), (c,w)]
__device__ float g_Btot[NN];                // fused bias

// ---------------------------------------------------------------------------
// Build Wtot[(v,i),(c,w)] = s_b[c]*sum_k A[k,c%8,v,w]*conv_w[k*CO+c,i]
//                         + sum_k RG[k,c%8,v,w]*s_d[o]*down_w[o,i]
// ---------------------------------------------------------------------------
__global__ void prep_w(const float* __restrict__ A_adj, const float* __restrict__ resg,
                       const float* __restrict__ conv_w, const float* __restrict__ down_w,
                       const float* __restrict__ dbn_g, const float* __restrict__ dbn_v,
                       const float* __restrict__ bn_g, const float* __restrict__ bn_v) {
    int row = blockIdx.x;          // (v,i): row = v*128 + i
    int v = row >> 7;
    int i = row & 127;
    for (int j = threadIdx.x; j < NN; j += blockDim.x) {
        int c = j / WW;
        int w = j - c * WW;
        int g = c & 7;
        float sb = bn_g[c] * rsqrtf(bn_v[c] + BN_EPS);
        float acc = 0.f;
#pragma unroll
        for (int k = 0; k < KG; k++) {
            int o = k * CO + c;
            int ai = ((k * GG + g) * VV + v) * WW + w;
            float a  = A_adj[ai];
            float rg = resg[ai];
            float sd = dbn_g[o] * rsqrtf(dbn_v[o] + BN_EPS);
            acc = fmaf(sb * a,  conv_w[o * CI + i], acc);
            acc = fmaf(rg * sd, down_w[o * CI + i], acc);
        }
        g_Wtot[(size_t)row * NN + j] = acc;
    }
}

// ---------------------------------------------------------------------------
// Btot[(c,w)] = s_b[c]*(sum_{k,v} A*conv_b[o]) + t_b[c] + sum_{k,v} RG*(down_b'[o])
// ---------------------------------------------------------------------------
__global__ void prep_b(const float* __restrict__ A_adj, const float* __restrict__ resg,
                       const float* __restrict__ conv_b, const float* __restrict__ down_b,
                       const float* __restrict__ dbn_g, const float* __restrict__ dbn_b,
                       const float* __restrict__ dbn_m, const float* __restrict__ dbn_v,
                       const float* __restrict__ bn_g, const float* __restrict__ bn_b,
                       const float* __restrict__ bn_m, const float* __restrict__ bn_v) {
    int j = blockIdx.x * blockDim.x + threadIdx.x;
    if (j >= NN) return;
    int c = j / WW;
    int w = j - c * WW;
    int g = c & 7;
    float sb = bn_g[c] * rsqrtf(bn_v[c] + BN_EPS);
    float tb = bn_b[c] - bn_m[c] * sb;
    float acc = tb;
#pragma unroll
    for (int k = 0; k < KG; k++) {
        int o = k * CO + c;
        float sd  = dbn_g[o] * rsqrtf(dbn_v[o] + BN_EPS);
        float td  = dbn_b[o] - dbn_m[o] * sd;
        float dbp = down_b[o] * sd + td;       // folded residual bias
        float cbs = sb * conv_b[o];            // folded main bias (bn scale applied)
        for (int v = 0; v < VV; v++) {
            int ai = ((k * GG + g) * VV + v) * WW + w;
            acc = fmaf(A_adj[ai], cbs, acc);
            acc = fmaf(resg[ai],  dbp, acc);
        }
    }
    g_Btot[j] = acc;
}

// ---------------------------------------------------------------------------
// Xs[(n*T+t)*KK + v*128 + i] = x[n,i,t,v]   (smem-tiled transpose)
// Block: fixed n, 4 t's, 32 i's, all 25 v's.
// ---------------------------------------------------------------------------
__global__ void transpose_x(const float* __restrict__ x) {
    __shared__ float s[32][101];   // padded: conflict-free on stride-100 reads
    int b  = blockIdx.x;
    int ib = b & 3;                // i block (4 x 32)
    int tb = (b >> 2) & 31;        // t block (32 x 4)
    int n  = b >> 7;
    int i0 = ib * 32;
    int t0 = tb * 4;
    const float* xp = x + (size_t)n * CI * TT * VV + (size_t)i0 * TT * VV + (size_t)t0 * VV;
    // load: per i-row, 100 contiguous floats (4 t's x 25 v's)
    for (int f = threadIdx.x; f < 3200; f += blockDim.x) {
        int il = f / 100;
        int q  = f - il * 100;
        s[il][q] = xp[(size_t)il * (TT * VV) + q];
    }
    __syncthreads();
    float* op = g_Xs + (size_t)(n * TT + t0) * KK + i0;
    // store: per (t,v), 32 contiguous i's
    for (int f = threadIdx.x; f < 3200; f += blockDim.x) {
        int tl = f / 800;
        int r  = f - tl * 800;
        int v  = r >> 5;
        int il = r & 31;
        op[(size_t)tl * KK + v * 128 + il] = s[il][tl * VV + v];
    }
}

// ---------------------------------------------------------------------------
// SGEMM 128x128x8, 256 threads, 8x8 per thread.
// C[m=(n,t), j=(c,w)] = relu( A[m,:] . B[:,j] + Btot[j] ), scattered to NCHW out.
// ---------------------------------------------------------------------------
__global__ __launch_bounds__(256) void gemm_relu(float* __restrict__ out) {
    __shared__ float As[8][128];
    __shared__ float Bs[8][128];
    const int m0 = blockIdx.y * 128;
    const int n0 = blockIdx.x * 128;
    const int tid = threadIdx.x;
    const int ty = tid >> 4, tx = tid & 15;
    const int rowB = ty * 8, colB = tx * 8;

    const int a_r = tid >> 1, a_c = (tid & 1) * 4;   // A tile: 128 rows x 8 cols
    const int b_r = tid >> 5, b_c = (tid & 31) * 4;  // B tile: 8 rows x 128 cols
    const float* Aptr = g_Xs  + (size_t)(m0 + a_r) * KK + a_c;
    const float* Bptr = g_Wtot + (size_t)b_r * NN + n0 + b_c;

    float acc[8][8];
#pragma unroll
    for (int r = 0; r < 8; r++)
#pragma unroll
        for (int c = 0; c < 8; c++) acc[r][c] = 0.f;

    for (int k0 = 0; k0 < KK; k0 += 8) {
        float4 av = *(const float4*)(Aptr + k0);
        As[a_c + 0][a_r] = av.x;
        As[a_c + 1][a_r] = av.y;
        As[a_c + 2][a_r] = av.z;
        As[a_c + 3][a_r] = av.w;
        float4 bv = *(const float4*)(Bptr + (size_t)k0 * NN);
        *(float4*)&Bs[b_r][b_c] = bv;
        __syncthreads();
#pragma unroll
        for (int kk = 0; kk < 8; kk++) {
            float a[8], b[8];
#pragma unroll
            for (int r = 0; r < 8; r++) a[r] = As[kk][rowB + r];
#pragma unroll
            for (int c = 0; c < 8; c++) b[c] = Bs[kk][colB + c];
#pragma unroll
            for (int r = 0; r < 8; r++)
#pragma unroll
                for (int c = 0; c < 8; c++) acc[r][c] = fmaf(a[r], b[c], acc[r][c]);
        }
        __syncthreads();
    }

    // epilogue: bias + relu + scatter to out[n, c, t, w]
#pragma unroll
    for (int cc = 0; cc < 8; cc++) {
        int j = n0 + colB + cc;
        int c = j / WW;
        int w = j - c * WW;
        float bb = g_Btot[j];
        size_t obase = (size_t)c * (TT * WW) + w;
#pragma unroll
        for (int r = 0; r < 8; r++) {
            int m = m0 + rowB + r;
            int n = m >> 7;
            int t = m & 127;
            float val = acc[r][cc] + bb;
            out[(size_t)n * (CO * TT * WW) + obase + (size_t)t * WW] = fmaxf(val, 0.f);
        }
    }
}

// ---------------------------------------------------------------------------
extern "C" void kernel_launch(void* const* d_in, const int* in_sizes, int n_in,
                              void* d_out, int out_size) {
    const float* x      = (const float*)d_in[0];
    const float* A_adj  = (const float*)d_in[1];
    const float* resg   = (const float*)d_in[2];
    const float* conv_w = (const float*)d_in[3];
    const float* conv_b = (const float*)d_in[4];
    const float* down_w = (const float*)d_in[5];
    const float* down_b = (const float*)d_in[6];
    const float* dbn_g  = (const float*)d_in[7];
    const float* dbn_b  = (const float*)d_in[8];
    const float* dbn_m  = (const float*)d_in[9];
    const float* dbn_v  = (const float*)d_in[10];
    const float* bn_g   = (const float*)d_in[11];
    const float* bn_b   = (const float*)d_in[12];
    const float* bn_m   = (const float*)d_in[13];
    const float* bn_v   = (const float*)d_in[14];
    float* out = (float*)d_out;

    prep_w<<<KK, 256>>>(A_adj, resg, conv_w, down_w, dbn_g, dbn_v, bn_g, bn_v);
    prep_b<<<(NN + 255) / 256, 256>>>(A_adj, resg, conv_b, down_b,
                                      dbn_g, dbn_b, dbn_m, dbn_v,
                                      bn_g, bn_b, bn_m, bn_v);
    transpose_x<<<2048, 256>>>(x);
    dim3 grid(NN / 128, MM / 128);   // 22 x 16
    gemm_relu<<<grid, 256>>>(out);
}

// round 7
// speedup vs baseline: 1.0059x; 1.0059x over previous
#include <cuda_runtime.h>

// Problem constants
#define NB   16      // batch
#define CI   128     // in channels
#define CO   256     // out channels
#define TT   128     // time
#define VV   25      // joints
#define WW   11      // parts
#define KG   3       // graph kernels
#define GG   8       // groups
#define MM   2048    // NB*TT
#define KK   3200    // VV*CI
#define NN   2816    // CO*WW
#define BN_EPS 1e-5f

// Scratch (static device globals — allocation-free contract)
__device__ float g_Xs[(size_t)MM * KK];     // 26 MB : x transposed to [(n,t), (v,i)]
__device__ float g_Wtot[(size_t)KK * NN];   // 36 MB : fused weight [(v,i), (c,w)]
__device__ float g_Btot[NN];                // fused bias

// ---------------------------------------------------------------------------
// Build Wtot[(v,i),(c,w)] = s_b[c]*sum_k A[k,c%8,v,w]*conv_w[k*CO+c,i]
//                         + sum_k RG[k,c%8,v,w]*s_d[o]*down_w[o,i]
// ---------------------------------------------------------------------------
__global__ void prep_w(const float* __restrict__ A_adj, const float* __restrict__ resg,
                       const float* __restrict__ conv_w, const float* __restrict__ down_w,
                       const float* __restrict__ dbn_g, const float* __restrict__ dbn_v,
                       const float* __restrict__ bn_g, const float* __restrict__ bn_v) {
    int row = blockIdx.x;          // (v,i): row = v*128 + i
    int v = row >> 7;
    int i = row & 127;
    for (int j = threadIdx.x; j < NN; j += blockDim.x) {
        int c = j / WW;
        int w = j - c * WW;
        int g = c & 7;
        float sb = bn_g[c] * rsqrtf(bn_v[c] + BN_EPS);
        float acc = 0.f;
#pragma unroll
        for (int k = 0; k < KG; k++) {
            int o = k * CO + c;
            int ai = ((k * GG + g) * VV + v) * WW + w;
            float a  = A_adj[ai];
            float rg = resg[ai];
            float sd = dbn_g[o] * rsqrtf(dbn_v[o] + BN_EPS);
            acc = fmaf(sb * a,  conv_w[o * CI + i], acc);
            acc = fmaf(rg * sd, down_w[o * CI + i], acc);
        }
        g_Wtot[(size_t)row * NN + j] = acc;
    }
}

// ---------------------------------------------------------------------------
// Btot[(c,w)] = s_b[c]*(sum_{k,v} A*conv_b[o]) + t_b[c] + sum_{k,v} RG*(down_b'[o])
// ---------------------------------------------------------------------------
__global__ void prep_b(const float* __restrict__ A_adj, const float* __restrict__ resg,
                       const float* __restrict__ conv_b, const float* __restrict__ down_b,
                       const float* __restrict__ dbn_g, const float* __restrict__ dbn_b,
                       const float* __restrict__ dbn_m, const float* __restrict__ dbn_v,
                       const float* __restrict__ bn_g, const float* __restrict__ bn_b,
                       const float* __restrict__ bn_m, const float* __restrict__ bn_v) {
    int j = blockIdx.x * blockDim.x + threadIdx.x;
    if (j >= NN) return;
    int c = j / WW;
    int w = j - c * WW;
    int g = c & 7;
    float sb = bn_g[c] * rsqrtf(bn_v[c] + BN_EPS);
    float tb = bn_b[c] - bn_m[c] * sb;
    float acc = tb;
#pragma unroll
    for (int k = 0; k < KG; k++) {
        int o = k * CO + c;
        float sd  = dbn_g[o] * rsqrtf(dbn_v[o] + BN_EPS);
        float td  = dbn_b[o] - dbn_m[o] * sd;
        float dbp = down_b[o] * sd + td;       // folded residual bias
        float cbs = sb * conv_b[o];            // folded main bias (bn scale applied)
        for (int v = 0; v < VV; v++) {
            int ai = ((k * GG + g) * VV + v) * WW + w;
            acc = fmaf(A_adj[ai], cbs, acc);
            acc = fmaf(resg[ai],  dbp, acc);
        }
    }
    g_Btot[j] = acc;
}

// ---------------------------------------------------------------------------
// Xs[(n*T+t)*KK + v*128 + i] = x[n,i,t,v]   (smem-tiled transpose)
// Block: fixed n, 4 t's, 32 i's, all 25 v's.
// ---------------------------------------------------------------------------
__global__ void transpose_x(const float* __restrict__ x) {
    __shared__ float s[32][101];   // padded: conflict-free on stride-100 reads
    int b  = blockIdx.x;
    int ib = b & 3;                // i block (4 x 32)
    int tb = (b >> 2) & 31;        // t block (32 x 4)
    int n  = b >> 7;
    int i0 = ib * 32;
    int t0 = tb * 4;
    const float* xp = x + (size_t)n * CI * TT * VV + (size_t)i0 * TT * VV + (size_t)t0 * VV;
    // load: per i-row, 100 contiguous floats (4 t's x 25 v's)
    for (int f = threadIdx.x; f < 3200; f += blockDim.x) {
        int il = f / 100;
        int q  = f - il * 100;
        s[il][q] = xp[(size_t)il * (TT * VV) + q];
    }
    __syncthreads();
    float* op = g_Xs + (size_t)(n * TT + t0) * KK + i0;
    // store: per (t,v), 32 contiguous i's
    for (int f = threadIdx.x; f < 3200; f += blockDim.x) {
        int tl = f / 800;
        int r  = f - tl * 800;
        int v  = r >> 5;
        int il = r & 31;
        op[(size_t)tl * KK + v * 128 + il] = s[il][tl * VV + v];
    }
}

// ---------------------------------------------------------------------------
// SGEMM 128x128x8, 256 threads, 8x8 per thread.
// C[m=(n,t), j=(c,w)] = relu( A[m,:] . B[:,j] + Btot[j] ), scattered to NCHW out.
// ---------------------------------------------------------------------------
__global__ __launch_bounds__(256) void gemm_relu(float* __restrict__ out) {
    __shared__ float As[8][128];
    __shared__ float Bs[8][128];
    const int m0 = blockIdx.y * 128;
    const int n0 = blockIdx.x * 128;
    const int tid = threadIdx.x;
    const int ty = tid >> 4, tx = tid & 15;
    const int rowB = ty * 8, colB = tx * 8;

    const int a_r = tid >> 1, a_c = (tid & 1) * 4;   // A tile: 128 rows x 8 cols
    const int b_r = tid >> 5, b_c = (tid & 31) * 4;  // B tile: 8 rows x 128 cols
    const float* Aptr = g_Xs  + (size_t)(m0 + a_r) * KK + a_c;
    const float* Bptr = g_Wtot + (size_t)b_r * NN + n0 + b_c;

    float acc[8][8];
#pragma unroll
    for (int r = 0; r < 8; r++)
#pragma unroll
        for (int c = 0; c < 8; c++) acc[r][c] = 0.f;

    for (int k0 = 0; k0 < KK; k0 += 8) {
        float4 av = *(const float4*)(Aptr + k0);
        As[a_c + 0][a_r] = av.x;
        As[a_c + 1][a_r] = av.y;
        As[a_c + 2][a_r] = av.z;
        As[a_c + 3][a_r] = av.w;
        float4 bv = *(const float4*)(Bptr + (size_t)k0 * NN);
        *(float4*)&Bs[b_r][b_c] = bv;
        __syncthreads();
#pragma unroll
        for (int kk = 0; kk < 8; kk++) {
            float a[8], b[8];
#pragma unroll
            for (int r = 0; r < 8; r++) a[r] = As[kk][rowB + r];
#pragma unroll
            for (int c = 0; c < 8; c++) b[c] = Bs[kk][colB + c];
#pragma unroll
            for (int r = 0; r < 8; r++)
#pragma unroll
                for (int c = 0; c < 8; c++) acc[r][c] = fmaf(a[r], b[c], acc[r][c]);
        }
        __syncthreads();
    }

    // epilogue: bias + relu + scatter to out[n, c, t, w]
#pragma unroll
    for (int cc = 0; cc < 8; cc++) {
        int j = n0 + colB + cc;
        int c = j / WW;
        int w = j - c * WW;
        float bb = g_Btot[j];
        size_t obase = (size_t)c * (TT * WW) + w;
#pragma unroll
        for (int r = 0; r < 8; r++) {
            int m = m0 + rowB + r;
            int n = m >> 7;
            int t = m & 127;
            float val = acc[r][cc] + bb;
            out[(size_t)n * (CO * TT * WW) + obase + (size_t)t * WW] = fmaxf(val, 0.f);
        }
    }
}

// ---------------------------------------------------------------------------
extern "C" void kernel_launch(void* const* d_in, const int* in_sizes, int n_in,
                              void* d_out, int out_size) {
    const float* x      = (const float*)d_in[0];
    const float* A_adj  = (const float*)d_in[1];
    const float* resg   = (const float*)d_in[2];
    const float* conv_w = (const float*)d_in[3];
    const float* conv_b = (const float*)d_in[4];
    const float* down_w = (const float*)d_in[5];
    const float* down_b = (const float*)d_in[6];
    const float* dbn_g  = (const float*)d_in[7];
    const float* dbn_b  = (const float*)d_in[8];
    const float* dbn_m  = (const float*)d_in[9];
    const float* dbn_v  = (const float*)d_in[10];
    const float* bn_g   = (const float*)d_in[11];
    const float* bn_b   = (const float*)d_in[12];
    const float* bn_m   = (const float*)d_in[13];
    const float* bn_v   = (const float*)d_in[14];
    float* out = (float*)d_out;

    prep_w<<<KK, 256>>>(A_adj, resg, conv_w, down_w, dbn_g, dbn_v, bn_g, bn_v);
    prep_b<<<(NN + 255) / 256, 256>>>(A_adj, resg, conv_b, down_b,
                                      dbn_g, dbn_b, dbn_m, dbn_v,
                                      bn_g, bn_b, bn_m, bn_v);
    transpose_x<<<2048, 256>>>(x);
    dim3 grid(NN / 128, MM / 128);   // 22 x 16
    gemm_relu<<<grid, 256>>>(out);
}